// round 10
// baseline (speedup 1.0000x reference)
#include <cuda_runtime.h>

#define LATENT  10
#define MAXLEN  80
#define BATCH   512
#define NSTEPS  100
#define HID     64
#define DTC     0.01f

typedef unsigned long long u64;
typedef unsigned int u32;

// ---------------- packed f32x2 helpers (sm_100+) ----------------
__device__ __forceinline__ u64 pk(float x, float y) {
    u64 r; asm("mov.b64 %0, {%1, %2};" : "=l"(r) : "f"(x), "f"(y)); return r;
}
__device__ __forceinline__ void upk(u64 a, float& x, float& y) {
    asm("mov.b64 {%0, %1}, %2;" : "=f"(x), "=f"(y) : "l"(a));
}
__device__ __forceinline__ u64 fma2_(u64 a, u64 b, u64 c) {
    u64 d; asm("fma.rn.f32x2 %0, %1, %2, %3;" : "=l"(d) : "l"(a), "l"(b), "l"(c)); return d;
}
__device__ __forceinline__ u64 mul2_(u64 a, u64 b) {
    u64 d; asm("mul.rn.f32x2 %0, %1, %2;" : "=l"(d) : "l"(a), "l"(b)); return d;
}
__device__ __forceinline__ u64 sub2_(u64 a, u64 b) {
    u64 d; asm("sub.rn.f32x2 %0, %1, %2;" : "=l"(d) : "l"(a), "l"(b)); return d;
}

// ---------------- tf32 helpers ----------------
__device__ __forceinline__ u32 cvt_tf32(float x) {
    u32 r; asm("cvt.rna.tf32.f32 %0, %1;" : "=r"(r) : "f"(x)); return r;
}

__device__ __forceinline__ void mma8(float* c, u32 a0, u32 a1, u32 a2, u32 a3,
                                     u32 b0, u32 b1) {
    asm("mma.sync.aligned.m16n8k8.row.col.f32.tf32.tf32.f32 "
        "{%0,%1,%2,%3}, {%4,%5,%6,%7}, {%8,%9}, {%0,%1,%2,%3};"
        : "+f"(c[0]), "+f"(c[1]), "+f"(c[2]), "+f"(c[3])
        : "r"(a0), "r"(a1), "r"(a2), "r"(a3), "r"(b0), "r"(b1));
}

// per-(chain, d) SDE constants
__device__ __forceinline__ void prep_cd(const float* __restrict__ zm,
                                        const float* __restrict__ zlv,
                                        int bb, int l, int d,
                                        float& mu, float& sinv, float& ssd) {
    const float* zmr = zm  + ((size_t)bb * MAXLEN + l) * LATENT;
    const float* zvr = zlv + ((size_t)bb * MAXLEN + l) * LATENT;
    float zmc = zmr[d];
    float zmp = (l > 0) ? zmr[d - LATENT] : 0.f;
    mu = zmc - zmp;
    float av = (l > 0) ? zvr[d - LATENT] : 0.f;
    float bv = zvr[d];
    float mx = fmaxf(av, bv);
    float sg = mx + log1pf(expf(-fabsf(av - bv)));   // logaddexp
    float sstd = expf(0.5f * sg);
    sinv = 1.f / sg;
    ssd  = sstd * 0.1f;                              // sigma_std * sqrt(dt)
}

// One warp = 32 chains (same l), processed as TWO independent 16-row M-tiles
// sharing the register-resident tf32 weight B-fragments. SDE state stays in
// MMA C-layout so score output fragments chain directly into next-step A
// fragments. Grid 1280 warps -> single resident wave on 148 SMs.
__global__ void __launch_bounds__(32, 8)
vae_mma4_kernel(const float* __restrict__ zm,
                const float* __restrict__ zlv,
                const float* __restrict__ W1,
                const float* __restrict__ b1,
                const float* __restrict__ W2,
                const float* __restrict__ b2,
                const float* __restrict__ noise,
                float* __restrict__ out)
{
    const int lane = threadIdx.x;
    const int r  = lane >> 2;
    const int gc = lane & 3;
    const int base = blockIdx.x * 32;
    const int l   = base >> 9;          // uniform per warp (32 | 512)
    const int bb0 = base & 511;

    // chain ids per tile T: rows r -> cT0, r+8 -> cT1
    const int cc[2][2] = {{bb0 + r, bb0 + r + 8}, {bb0 + 16 + r, bb0 + 24 + r}};

    // hidden-unit permutation: B-col n (=r) -> j_local
    const int jl = (r & 1) ? (r >> 1) + 4 : (r >> 1);

    // ---- static weight fragments (single tf32, shared by both tiles) ----
    u32 B1h0[8][2];                   // layer1 kt0 (features 0-7)
    u32 B1h1[8];                      // layer1 kt1 reg0 (features 8-11)
    u32 B2h[8][2][2];                 // layer2 [jt][nt][reg]

#pragma unroll
    for (int jt = 0; jt < 8; jt++) {
        int j = 8 * jt + jl;
        B1h0[jt][0] = cvt_tf32(W1[gc * HID + j]);
        B1h0[jt][1] = cvt_tf32(W1[(gc + 4) * HID + j]);
        float wt = (gc == 3) ? b1[j] : W1[(8 + gc) * HID + j];
        B1h1[jt] = cvt_tf32(wt);
#pragma unroll
        for (int nt = 0; nt < 2; nt++) {
            int d = (nt == 0) ? jl : ((jl < 2) ? 8 + jl : -1);
            float v0 = (d >= 0) ? W2[(8 * jt + gc) * LATENT + d]     : 0.f;
            float v1 = (d >= 0) ? W2[(8 * jt + gc + 4) * LATENT + d] : 0.f;
            B2h[jt][nt][0] = cvt_tf32(v0);
            B2h[jt][nt][1] = cvt_tf32(v1);
        }
    }

    // ---- SDE state in fragment layout, [tile][nt][half] ----
    u64 xt[2][2][2], mu2[2][2][2], sinv2[2][2][2], ssd2[2][2][2], err2[2][2][2];
#pragma unroll
    for (int T = 0; T < 2; T++)
#pragma unroll
    for (int h = 0; h < 2; h++) {
        int bb = cc[T][h];
        float m0, s0, w0, m1, s1, w1;
        prep_cd(zm, zlv, bb, l, gc,     m0, s0, w0);
        prep_cd(zm, zlv, bb, l, gc + 4, m1, s1, w1);
        mu2[T][0][h]   = pk(m0, m1);
        sinv2[T][0][h] = pk(s0, s1);
        ssd2[T][0][h]  = pk(w0, w1);
        xt[T][0][h]    = mu2[T][0][h];
        err2[T][0][h]  = 0ULL;
        if (gc < 2) {
            prep_cd(zm, zlv, bb, l, 8 + gc, m0, s0, w0);
        } else { m0 = 0.f; s0 = 0.f; w0 = 0.f; }
        mu2[T][1][h]   = pk(m0, 0.f);
        sinv2[T][1][h] = pk(s0, 0.f);
        ssd2[T][1][h]  = pk(w0, 0.f);
        xt[T][1][h]    = mu2[T][1][h];
        err2[T][1][h]  = 0ULL;
    }
    const u64 dt2 = pk(DTC, DTC);
    const u64 h05 = pk(0.5f, 0.5f);

    // bias values in S C-layout
    const float bs0 = b2[gc];
    const float bs1 = b2[gc + 4];
    const float bs2 = (gc < 2) ? b2[8 + gc] : 0.f;

    // noise pointers per tile (strength-reduced)
    const float* nz0 = noise + ((size_t)l * NSTEPS * BATCH + cc[0][0]) * LATENT;
    const float* nz1 = noise + ((size_t)l * NSTEPS * BATCH + cc[1][0]) * LATENT;
    const int nzstep = BATCH * LATENT;

#pragma unroll 1
    for (int s = 0; s < NSTEPS; s++) {
        const float tt = (float)(l + s) * DTC;

        // ---- noise gathers for both tiles ----
        u64 nzv[2][2][2];
#pragma unroll
        for (int T = 0; T < 2; T++) {
            const float* nA = (T == 0) ? nz0 : nz1;
            const float* nB = nA + 8 * LATENT;
            nzv[T][0][0] = pk(nA[gc], nA[gc + 4]);
            nzv[T][0][1] = pk(nB[gc], nB[gc + 4]);
            nzv[T][1][0] = (gc < 2) ? pk(nA[8 + gc], 0.f) : 0ULL;
            nzv[T][1][1] = (gc < 2) ? pk(nB[8 + gc], 0.f) : 0ULL;
        }
        nz0 += nzstep;
        nz1 += nzstep;

        // ---- build A fragments for both tiles ----
        u32 A[2][4], E[2][2];
#pragma unroll
        for (int T = 0; T < 2; T++) {
            float x0, x1, y0, y1;
            upk(xt[T][0][0], x0, x1);
            upk(xt[T][0][1], y0, y1);
            A[T][0] = cvt_tf32(x0);
            A[T][1] = cvt_tf32(y0);
            A[T][2] = cvt_tf32(x1);
            A[T][3] = cvt_tf32(y1);

            float xA8, xB8, dmy;
            upk(xt[T][1][0], xA8, dmy);
            upk(xt[T][1][1], xB8, dmy);
            float sA0 = __shfl_sync(0xffffffffu, xA8, lane & ~3);
            float sA1 = __shfl_sync(0xffffffffu, xA8, (lane & ~3) | 1);
            float sB0 = __shfl_sync(0xffffffffu, xB8, lane & ~3);
            float sB1 = __shfl_sync(0xffffffffu, xB8, (lane & ~3) | 1);
            float f0 = (gc == 0) ? sA0 : (gc == 1) ? sA1 : (gc == 2) ? tt : 1.0f;
            float f1 = (gc == 0) ? sB0 : (gc == 1) ? sB1 : (gc == 2) ? tt : 1.0f;
            E[T][0] = cvt_tf32(f0);
            E[T][1] = cvt_tf32(f1);
        }

        // ---- layer-2 accumulators, 4 independent chains (tile x nt) ----
        float S[2][2][4];
#pragma unroll
        for (int T = 0; T < 2; T++) {
            S[T][0][0] = bs0; S[T][0][1] = bs1; S[T][0][2] = bs0; S[T][0][3] = bs1;
            S[T][1][0] = bs2; S[T][1][1] = 0.f; S[T][1][2] = bs2; S[T][1][3] = 0.f;
        }

#pragma unroll
        for (int jt = 0; jt < 8; jt++) {
            // layer-1 for both tiles (independent chains)
            float C0[4] = {0.f, 0.f, 0.f, 0.f};
            float C1[4] = {0.f, 0.f, 0.f, 0.f};
            mma8(C0, A[0][0], A[0][1], A[0][2], A[0][3], B1h0[jt][0], B1h0[jt][1]);
            mma8(C1, A[1][0], A[1][1], A[1][2], A[1][3], B1h0[jt][0], B1h0[jt][1]);
            mma8(C0, E[0][0], E[0][1], 0u, 0u, B1h1[jt], 0u);
            mma8(C1, E[1][0], E[1][1], 0u, 0u, B1h1[jt], 0u);

            // relu + C->A fragment permute (c0,c2,c1,c3)
            u32 H0[4], H1[4];
            H0[0] = cvt_tf32(fmaxf(C0[0], 0.f));
            H0[1] = cvt_tf32(fmaxf(C0[2], 0.f));
            H0[2] = cvt_tf32(fmaxf(C0[1], 0.f));
            H0[3] = cvt_tf32(fmaxf(C0[3], 0.f));
            H1[0] = cvt_tf32(fmaxf(C1[0], 0.f));
            H1[1] = cvt_tf32(fmaxf(C1[2], 0.f));
            H1[2] = cvt_tf32(fmaxf(C1[1], 0.f));
            H1[3] = cvt_tf32(fmaxf(C1[3], 0.f));

            mma8(S[0][0], H0[0], H0[1], H0[2], H0[3], B2h[jt][0][0], B2h[jt][0][1]);
            mma8(S[1][0], H1[0], H1[1], H1[2], H1[3], B2h[jt][0][0], B2h[jt][0][1]);
            mma8(S[0][1], H0[0], H0[1], H0[2], H0[3], B2h[jt][1][0], B2h[jt][1][1]);
            mma8(S[1][1], H1[0], H1[1], H1[2], H1[3], B2h[jt][1][0], B2h[jt][1][1]);
        }

        // ---- SDE update + score error, both tiles ----
#pragma unroll
        for (int T = 0; T < 2; T++)
#pragma unroll
        for (int nt = 0; nt < 2; nt++) {
            u64 sc0 = pk(S[T][nt][0], S[T][nt][1]);
            u64 sc1 = pk(S[T][nt][2], S[T][nt][3]);
            u64 scp[2] = {sc0, sc1};
#pragma unroll
            for (int h = 0; h < 2; h++) {
                u64 logdx = mul2_(sub2_(mu2[T][nt][h], xt[T][nt][h]), sinv2[T][nt][h]);
                u64 diff  = sub2_(logdx, scp[h]);
                err2[T][nt][h] = fma2_(diff, diff, err2[T][nt][h]);
                u64 x  = fma2_(mu2[T][nt][h], dt2, xt[T][nt][h]);
                u64 t1 = mul2_(scp[h], ssd2[T][nt][h]);
                u64 t2 = mul2_(t1, ssd2[T][nt][h]);
                x = fma2_(t2, h05, x);                       // + 0.5*var*score*dt
                xt[T][nt][h] = fma2_(nzv[T][nt][h], ssd2[T][nt][h], x);
            }
        }
    }

    // ---- outputs (scatter from fragment layout) ----
    const float inv_n = 1.0f / (float)NSTEPS;
#pragma unroll
    for (int T = 0; T < 2; T++)
#pragma unroll
    for (int h = 0; h < 2; h++) {
        int bb = cc[T][h];
        float* oS = out + ((size_t)bb * MAXLEN + l) * LATENT;
        float* oE = oS + (size_t)BATCH * MAXLEN * LATENT;
        float x0, x1, e0, e1;
        upk(xt[T][0][h], x0, x1);
        upk(err2[T][0][h], e0, e1);
        oS[gc]     = x0;
        oS[gc + 4] = x1;
        oE[gc]     = e0 * inv_n;
        oE[gc + 4] = e1 * inv_n;
        if (gc < 2) {
            upk(xt[T][1][h], x0, x1);
            upk(err2[T][1][h], e0, e1);
            oS[8 + gc] = x0;
            oE[8 + gc] = e0 * inv_n;
        }
    }
}

extern "C" void kernel_launch(void* const* d_in, const int* in_sizes, int n_in,
                              void* d_out, int out_size)
{
    const float* zm    = (const float*)d_in[0];  // [512,80,10]
    const float* zlv   = (const float*)d_in[1];  // [512,80,10]
    const float* W1    = (const float*)d_in[2];  // [11,64]
    const float* b1    = (const float*)d_in[3];  // [64]
    const float* W2    = (const float*)d_in[4];  // [64,10]
    const float* b2    = (const float*)d_in[5];  // [10]
    const float* noise = (const float*)d_in[6];  // [80,100,512,10]
    float* out = (float*)d_out;                  // [2,512,80,10]

    const int nblocks = BATCH * MAXLEN / 32;     // 1280 warps, 32 chains each
    vae_mma4_kernel<<<nblocks, 32>>>(zm, zlv, W1, b1, W2, b2, noise, out);
}

// round 11
// speedup vs baseline: 1.4215x; 1.4215x over previous
#include <cuda_runtime.h>

#define LATENT  10
#define MAXLEN  80
#define BATCH   512
#define NSTEPS  100
#define HID     64
#define DTC     0.01f

typedef unsigned long long u64;
typedef unsigned int u32;

// ---------------- packed f32x2 helpers (sm_100+) ----------------
__device__ __forceinline__ u64 pk(float x, float y) {
    u64 r; asm("mov.b64 %0, {%1, %2};" : "=l"(r) : "f"(x), "f"(y)); return r;
}
__device__ __forceinline__ void upk(u64 a, float& x, float& y) {
    asm("mov.b64 {%0, %1}, %2;" : "=f"(x), "=f"(y) : "l"(a));
}
__device__ __forceinline__ u64 fma2_(u64 a, u64 b, u64 c) {
    u64 d; asm("fma.rn.f32x2 %0, %1, %2, %3;" : "=l"(d) : "l"(a), "l"(b), "l"(c)); return d;
}
__device__ __forceinline__ u64 mul2_(u64 a, u64 b) {
    u64 d; asm("mul.rn.f32x2 %0, %1, %2;" : "=l"(d) : "l"(a), "l"(b)); return d;
}
__device__ __forceinline__ u64 sub2_(u64 a, u64 b) {
    u64 d; asm("sub.rn.f32x2 %0, %1, %2;" : "=l"(d) : "l"(a), "l"(b)); return d;
}

// ---------------- tf32 helpers ----------------
__device__ __forceinline__ u32 cvt_tf32(float x) {
    u32 r; asm("cvt.rna.tf32.f32 %0, %1;" : "=r"(r) : "f"(x)); return r;
}

__device__ __forceinline__ void mma8(float* c, u32 a0, u32 a1, u32 a2, u32 a3,
                                     u32 b0, u32 b1) {
    asm("mma.sync.aligned.m16n8k8.row.col.f32.tf32.tf32.f32 "
        "{%0,%1,%2,%3}, {%4,%5,%6,%7}, {%8,%9}, {%0,%1,%2,%3};"
        : "+f"(c[0]), "+f"(c[1]), "+f"(c[2]), "+f"(c[3])
        : "r"(a0), "r"(a1), "r"(a2), "r"(a3), "r"(b0), "r"(b1));
}

// per-(chain, d) SDE constants
__device__ __forceinline__ void prep_cd(const float* __restrict__ zm,
                                        const float* __restrict__ zlv,
                                        int bb, int l, int d,
                                        float& mu, float& sinv, float& ssd) {
    const float* zmr = zm  + ((size_t)bb * MAXLEN + l) * LATENT;
    const float* zvr = zlv + ((size_t)bb * MAXLEN + l) * LATENT;
    float zmc = zmr[d];
    float zmp = (l > 0) ? zmr[d - LATENT] : 0.f;
    mu = zmc - zmp;
    float av = (l > 0) ? zvr[d - LATENT] : 0.f;
    float bv = zvr[d];
    float mx = fmaxf(av, bv);
    float sg = mx + log1pf(expf(-fabsf(av - bv)));   // logaddexp
    float sstd = expf(0.5f * sg);
    sinv = 1.f / sg;
    ssd  = sstd * 0.1f;                              // sigma_std * sqrt(dt)
}

// SMEM constant slot index: c in {0:mu, 1:sinv, 2:ssd}
#define CSLOT(c, T, nt, h) ((((c) * 2 + (T)) * 2 + (nt)) * 2 + (h))

// One warp = 32 chains (same l), TWO independent 16-row M-tiles sharing the
// register-resident tf32 weight B-fragments. Read-only SDE constants
// (mu, sinv, ssd) live in per-thread SMEM to keep registers under the
// 9-CTA/SM residency limit (grid 1280 -> true single wave on 148 SMs).
// Layer-2 uses 8 independent accumulator chains (tile x nt x jt-parity).
__global__ void __launch_bounds__(32, 9)
vae_mma5_kernel(const float* __restrict__ zm,
                const float* __restrict__ zlv,
                const float* __restrict__ W1,
                const float* __restrict__ b1,
                const float* __restrict__ W2,
                const float* __restrict__ b2,
                const float* __restrict__ noise,
                float* __restrict__ out)
{
    __shared__ __align__(16) u64 sC[24][32];     // 6 KB: [slot][lane]

    const int lane = threadIdx.x;
    const int r  = lane >> 2;
    const int gc = lane & 3;
    const int base = blockIdx.x * 32;
    const int l   = base >> 9;          // uniform per warp (32 | 512)
    const int bb0 = base & 511;

    // chain ids per tile T: rows r -> cc[T][0], r+8 -> cc[T][1]
    const int cc[2][2] = {{bb0 + r, bb0 + r + 8}, {bb0 + 16 + r, bb0 + 24 + r}};

    // hidden-unit permutation: B-col n (=r) -> j_local
    const int jl = (r & 1) ? (r >> 1) + 4 : (r >> 1);

    // ---- static weight fragments (single tf32, shared by both tiles) ----
    u32 B1h0[8][2];                   // layer1 kt0 (features 0-7)
    u32 B1h1[8];                      // layer1 kt1 reg0 (features 8-11)
    u32 B2h[8][2][2];                 // layer2 [jt][nt][reg]

#pragma unroll
    for (int jt = 0; jt < 8; jt++) {
        int j = 8 * jt + jl;
        B1h0[jt][0] = cvt_tf32(W1[gc * HID + j]);
        B1h0[jt][1] = cvt_tf32(W1[(gc + 4) * HID + j]);
        float wt = (gc == 3) ? b1[j] : W1[(8 + gc) * HID + j];
        B1h1[jt] = cvt_tf32(wt);
#pragma unroll
        for (int nt = 0; nt < 2; nt++) {
            int d = (nt == 0) ? jl : ((jl < 2) ? 8 + jl : -1);
            float v0 = (d >= 0) ? W2[(8 * jt + gc) * LATENT + d]     : 0.f;
            float v1 = (d >= 0) ? W2[(8 * jt + gc + 4) * LATENT + d] : 0.f;
            B2h[jt][nt][0] = cvt_tf32(v0);
            B2h[jt][nt][1] = cvt_tf32(v1);
        }
    }

    // ---- SDE state: xt/err in regs; mu/sinv/ssd in SMEM ----
    u64 xt[2][2][2], err2[2][2][2];
#pragma unroll
    for (int T = 0; T < 2; T++)
#pragma unroll
    for (int h = 0; h < 2; h++) {
        int bb = cc[T][h];
        float m0, s0, w0, m1, s1, w1;
        prep_cd(zm, zlv, bb, l, gc,     m0, s0, w0);
        prep_cd(zm, zlv, bb, l, gc + 4, m1, s1, w1);
        u64 mu = pk(m0, m1);
        sC[CSLOT(0, T, 0, h)][lane] = mu;
        sC[CSLOT(1, T, 0, h)][lane] = pk(s0, s1);
        sC[CSLOT(2, T, 0, h)][lane] = pk(w0, w1);
        xt[T][0][h]  = mu;
        err2[T][0][h] = 0ULL;
        if (gc < 2) {
            prep_cd(zm, zlv, bb, l, 8 + gc, m0, s0, w0);
        } else { m0 = 0.f; s0 = 0.f; w0 = 0.f; }
        mu = pk(m0, 0.f);
        sC[CSLOT(0, T, 1, h)][lane] = mu;
        sC[CSLOT(1, T, 1, h)][lane] = pk(s0, 0.f);
        sC[CSLOT(2, T, 1, h)][lane] = pk(w0, 0.f);
        xt[T][1][h]  = mu;
        err2[T][1][h] = 0ULL;
    }
    __syncwarp();

    const u64 dt2 = pk(DTC, DTC);
    const u64 h05 = pk(0.5f, 0.5f);

    // bias values in S C-layout
    const float bs0 = b2[gc];
    const float bs1 = b2[gc + 4];
    const float bs2 = (gc < 2) ? b2[8 + gc] : 0.f;

    // noise pointers per tile
    const float* nz0 = noise + ((size_t)l * NSTEPS * BATCH + cc[0][0]) * LATENT;
    const float* nz1 = noise + ((size_t)l * NSTEPS * BATCH + cc[1][0]) * LATENT;
    const int nzstep = BATCH * LATENT;

#pragma unroll 1
    for (int s = 0; s < NSTEPS; s++) {
        const float tt = (float)(l + s) * DTC;

        // ---- noise gathers for both tiles (prefetch ahead of MMA work) ----
        u64 nzv[2][2][2];
#pragma unroll
        for (int T = 0; T < 2; T++) {
            const float* nA = (T == 0) ? nz0 : nz1;
            const float* nB = nA + 8 * LATENT;
            nzv[T][0][0] = pk(nA[gc], nA[gc + 4]);
            nzv[T][0][1] = pk(nB[gc], nB[gc + 4]);
            nzv[T][1][0] = (gc < 2) ? pk(nA[8 + gc], 0.f) : 0ULL;
            nzv[T][1][1] = (gc < 2) ? pk(nB[8 + gc], 0.f) : 0ULL;
        }
        nz0 += nzstep;
        nz1 += nzstep;

        // ---- build A fragments for both tiles ----
        u32 A[2][4], E[2][2];
#pragma unroll
        for (int T = 0; T < 2; T++) {
            float x0, x1, y0, y1;
            upk(xt[T][0][0], x0, x1);
            upk(xt[T][0][1], y0, y1);
            A[T][0] = cvt_tf32(x0);
            A[T][1] = cvt_tf32(y0);
            A[T][2] = cvt_tf32(x1);
            A[T][3] = cvt_tf32(y1);

            float xA8, xB8, dmy;
            upk(xt[T][1][0], xA8, dmy);
            upk(xt[T][1][1], xB8, dmy);
            float sA0 = __shfl_sync(0xffffffffu, xA8, lane & ~3);
            float sA1 = __shfl_sync(0xffffffffu, xA8, (lane & ~3) | 1);
            float sB0 = __shfl_sync(0xffffffffu, xB8, lane & ~3);
            float sB1 = __shfl_sync(0xffffffffu, xB8, (lane & ~3) | 1);
            float f0 = (gc == 0) ? sA0 : (gc == 1) ? sA1 : (gc == 2) ? tt : 1.0f;
            float f1 = (gc == 0) ? sB0 : (gc == 1) ? sB1 : (gc == 2) ? tt : 1.0f;
            E[T][0] = cvt_tf32(f0);
            E[T][1] = cvt_tf32(f1);
        }

        // ---- layer-2 accumulators: 8 chains (tile x nt x jt-parity) ----
        float S[2][2][2][4];
#pragma unroll
        for (int T = 0; T < 2; T++) {
            S[T][0][0][0] = bs0; S[T][0][0][1] = bs1; S[T][0][0][2] = bs0; S[T][0][0][3] = bs1;
            S[T][1][0][0] = bs2; S[T][1][0][1] = 0.f; S[T][1][0][2] = bs2; S[T][1][0][3] = 0.f;
#pragma unroll
            for (int q = 0; q < 4; q++) { S[T][0][1][q] = 0.f; S[T][1][1][q] = 0.f; }
        }

#pragma unroll
        for (int jt = 0; jt < 8; jt++) {
            const int par = jt & 1;
            // layer-1 for both tiles (independent chains)
            float C0[4] = {0.f, 0.f, 0.f, 0.f};
            float C1[4] = {0.f, 0.f, 0.f, 0.f};
            mma8(C0, A[0][0], A[0][1], A[0][2], A[0][3], B1h0[jt][0], B1h0[jt][1]);
            mma8(C1, A[1][0], A[1][1], A[1][2], A[1][3], B1h0[jt][0], B1h0[jt][1]);
            mma8(C0, E[0][0], E[0][1], 0u, 0u, B1h1[jt], 0u);
            mma8(C1, E[1][0], E[1][1], 0u, 0u, B1h1[jt], 0u);

            // relu + C->A fragment permute (c0,c2,c1,c3)
            u32 H0[4], H1[4];
            H0[0] = cvt_tf32(fmaxf(C0[0], 0.f));
            H0[1] = cvt_tf32(fmaxf(C0[2], 0.f));
            H0[2] = cvt_tf32(fmaxf(C0[1], 0.f));
            H0[3] = cvt_tf32(fmaxf(C0[3], 0.f));
            H1[0] = cvt_tf32(fmaxf(C1[0], 0.f));
            H1[1] = cvt_tf32(fmaxf(C1[2], 0.f));
            H1[2] = cvt_tf32(fmaxf(C1[1], 0.f));
            H1[3] = cvt_tf32(fmaxf(C1[3], 0.f));

            mma8(S[0][0][par], H0[0], H0[1], H0[2], H0[3], B2h[jt][0][0], B2h[jt][0][1]);
            mma8(S[1][0][par], H1[0], H1[1], H1[2], H1[3], B2h[jt][0][0], B2h[jt][0][1]);
            mma8(S[0][1][par], H0[0], H0[1], H0[2], H0[3], B2h[jt][1][0], B2h[jt][1][1]);
            mma8(S[1][1][par], H1[0], H1[1], H1[2], H1[3], B2h[jt][1][0], B2h[jt][1][1]);
        }

        // ---- SDE update + score error, both tiles ----
#pragma unroll
        for (int T = 0; T < 2; T++)
#pragma unroll
        for (int nt = 0; nt < 2; nt++) {
            u64 sc0 = pk(S[T][nt][0][0] + S[T][nt][1][0],
                         S[T][nt][0][1] + S[T][nt][1][1]);
            u64 sc1 = pk(S[T][nt][0][2] + S[T][nt][1][2],
                         S[T][nt][0][3] + S[T][nt][1][3]);
            u64 scp[2] = {sc0, sc1};
#pragma unroll
            for (int h = 0; h < 2; h++) {
                u64 mu   = sC[CSLOT(0, T, nt, h)][lane];
                u64 sinv = sC[CSLOT(1, T, nt, h)][lane];
                u64 ssd  = sC[CSLOT(2, T, nt, h)][lane];
                u64 logdx = mul2_(sub2_(mu, xt[T][nt][h]), sinv);
                u64 diff  = sub2_(logdx, scp[h]);
                err2[T][nt][h] = fma2_(diff, diff, err2[T][nt][h]);
                u64 x  = fma2_(mu, dt2, xt[T][nt][h]);
                u64 t1 = mul2_(scp[h], ssd);
                u64 t2 = mul2_(t1, ssd);
                x = fma2_(t2, h05, x);                       // + 0.5*var*score*dt
                xt[T][nt][h] = fma2_(nzv[T][nt][h], ssd, x);
            }
        }
    }

    // ---- outputs (scatter from fragment layout) ----
    const float inv_n = 1.0f / (float)NSTEPS;
#pragma unroll
    for (int T = 0; T < 2; T++)
#pragma unroll
    for (int h = 0; h < 2; h++) {
        int bb = cc[T][h];
        float* oS = out + ((size_t)bb * MAXLEN + l) * LATENT;
        float* oE = oS + (size_t)BATCH * MAXLEN * LATENT;
        float x0, x1, e0, e1;
        upk(xt[T][0][h], x0, x1);
        upk(err2[T][0][h], e0, e1);
        oS[gc]     = x0;
        oS[gc + 4] = x1;
        oE[gc]     = e0 * inv_n;
        oE[gc + 4] = e1 * inv_n;
        if (gc < 2) {
            upk(xt[T][1][h], x0, x1);
            upk(err2[T][1][h], e0, e1);
            oS[8 + gc] = x0;
            oE[8 + gc] = e0 * inv_n;
        }
    }
}

extern "C" void kernel_launch(void* const* d_in, const int* in_sizes, int n_in,
                              void* d_out, int out_size)
{
    const float* zm    = (const float*)d_in[0];  // [512,80,10]
    const float* zlv   = (const float*)d_in[1];  // [512,80,10]
    const float* W1    = (const float*)d_in[2];  // [11,64]
    const float* b1    = (const float*)d_in[3];  // [64]
    const float* W2    = (const float*)d_in[4];  // [64,10]
    const float* b2    = (const float*)d_in[5];  // [10]
    const float* noise = (const float*)d_in[6];  // [80,100,512,10]
    float* out = (float*)d_out;                  // [2,512,80,10]

    const int nblocks = BATCH * MAXLEN / 32;     // 1280 warps, 32 chains each
    vae_mma5_kernel<<<nblocks, 32>>>(zm, zlv, W1, b1, W2, b2, noise, out);
}

// round 12
// speedup vs baseline: 1.4985x; 1.0542x over previous
#include <cuda_runtime.h>

#define LATENT  10
#define MAXLEN  80
#define BATCH   512
#define NSTEPS  100
#define HID     64
#define DTC     0.01f

typedef unsigned long long u64;
typedef unsigned int u32;

// ---------------- packed f32x2 helpers (sm_100+) ----------------
__device__ __forceinline__ u64 pk(float x, float y) {
    u64 r; asm("mov.b64 %0, {%1, %2};" : "=l"(r) : "f"(x), "f"(y)); return r;
}
__device__ __forceinline__ void upk(u64 a, float& x, float& y) {
    asm("mov.b64 {%0, %1}, %2;" : "=f"(x), "=f"(y) : "l"(a));
}
__device__ __forceinline__ u64 fma2_(u64 a, u64 b, u64 c) {
    u64 d; asm("fma.rn.f32x2 %0, %1, %2, %3;" : "=l"(d) : "l"(a), "l"(b), "l"(c)); return d;
}
__device__ __forceinline__ u64 mul2_(u64 a, u64 b) {
    u64 d; asm("mul.rn.f32x2 %0, %1, %2;" : "=l"(d) : "l"(a), "l"(b)); return d;
}
__device__ __forceinline__ u64 sub2_(u64 a, u64 b) {
    u64 d; asm("sub.rn.f32x2 %0, %1, %2;" : "=l"(d) : "l"(a), "l"(b)); return d;
}

// ---------------- tf32 helpers ----------------
// Weights (converted once at setup): proper rna conversion.
__device__ __forceinline__ u32 cvt_tf32(float x) {
    u32 r; asm("cvt.rna.tf32.f32 %0, %1;" : "=r"(r) : "f"(x)); return r;
}
// Loop operands: raw fp32 bits — HMMA.TF32 ignores the low mantissa bits
// (effective truncation). Saves the per-step cvt storm.
__device__ __forceinline__ u32 as_u32(float x) { return __float_as_uint(x); }

__device__ __forceinline__ void mma8(float* c, u32 a0, u32 a1, u32 a2, u32 a3,
                                     u32 b0, u32 b1) {
    asm("mma.sync.aligned.m16n8k8.row.col.f32.tf32.tf32.f32 "
        "{%0,%1,%2,%3}, {%4,%5,%6,%7}, {%8,%9}, {%0,%1,%2,%3};"
        : "+f"(c[0]), "+f"(c[1]), "+f"(c[2]), "+f"(c[3])
        : "r"(a0), "r"(a1), "r"(a2), "r"(a3), "r"(b0), "r"(b1));
}

// per-(chain, d) SDE constants
__device__ __forceinline__ void prep_cd(const float* __restrict__ zm,
                                        const float* __restrict__ zlv,
                                        int bb, int l, int d,
                                        float& mu, float& sinv, float& ssd) {
    const float* zmr = zm  + ((size_t)bb * MAXLEN + l) * LATENT;
    const float* zvr = zlv + ((size_t)bb * MAXLEN + l) * LATENT;
    float zmc = zmr[d];
    float zmp = (l > 0) ? zmr[d - LATENT] : 0.f;
    mu = zmc - zmp;
    float av = (l > 0) ? zvr[d - LATENT] : 0.f;
    float bv = zvr[d];
    float mx = fmaxf(av, bv);
    float sg = mx + log1pf(expf(-fabsf(av - bv)));   // logaddexp
    float sstd = expf(0.5f * sg);
    sinv = 1.f / sg;
    ssd  = sstd * 0.1f;                              // sigma_std * sqrt(dt)
}

// SMEM constant slot index: c in {0:mu, 1:sinv, 2:ssd}
#define CSLOT(c, T, nt, h) ((((c) * 2 + (T)) * 2 + (nt)) * 2 + (h))

// One warp = 32 chains (same l), TWO independent 16-row M-tiles sharing the
// register-resident tf32 weight B-fragments. Read-only SDE constants in
// per-thread SMEM. MLP loop feeds raw fp32 bits to HMMA.TF32 (no cvt).
__global__ void __launch_bounds__(32, 9)
vae_mma6_kernel(const float* __restrict__ zm,
                const float* __restrict__ zlv,
                const float* __restrict__ W1,
                const float* __restrict__ b1,
                const float* __restrict__ W2,
                const float* __restrict__ b2,
                const float* __restrict__ noise,
                float* __restrict__ out)
{
    __shared__ __align__(16) u64 sC[24][32];     // 6 KB: [slot][lane]

    const int lane = threadIdx.x;
    const int r  = lane >> 2;
    const int gc = lane & 3;
    const int base = blockIdx.x * 32;
    const int l   = base >> 9;          // uniform per warp (32 | 512)
    const int bb0 = base & 511;

    // chain ids per tile T: rows r -> cc[T][0], r+8 -> cc[T][1]
    const int cc[2][2] = {{bb0 + r, bb0 + r + 8}, {bb0 + 16 + r, bb0 + 24 + r}};

    // hidden-unit permutation: B-col n (=r) -> j_local
    const int jl = (r & 1) ? (r >> 1) + 4 : (r >> 1);

    // ---- static weight fragments (single tf32, shared by both tiles) ----
    u32 B1h0[8][2];                   // layer1 kt0 (features 0-7)
    u32 B1h1[8];                      // layer1 kt1 reg0 (features 8-11)
    u32 B2h[8][2][2];                 // layer2 [jt][nt][reg]

#pragma unroll
    for (int jt = 0; jt < 8; jt++) {
        int j = 8 * jt + jl;
        B1h0[jt][0] = cvt_tf32(W1[gc * HID + j]);
        B1h0[jt][1] = cvt_tf32(W1[(gc + 4) * HID + j]);
        float wt = (gc == 3) ? b1[j] : W1[(8 + gc) * HID + j];
        B1h1[jt] = cvt_tf32(wt);
#pragma unroll
        for (int nt = 0; nt < 2; nt++) {
            int d = (nt == 0) ? jl : ((jl < 2) ? 8 + jl : -1);
            float v0 = (d >= 0) ? W2[(8 * jt + gc) * LATENT + d]     : 0.f;
            float v1 = (d >= 0) ? W2[(8 * jt + gc + 4) * LATENT + d] : 0.f;
            B2h[jt][nt][0] = cvt_tf32(v0);
            B2h[jt][nt][1] = cvt_tf32(v1);
        }
    }

    // ---- SDE state: xt/err in regs; mu/sinv/ssd in SMEM ----
    u64 xt[2][2][2], err2[2][2][2];
#pragma unroll
    for (int T = 0; T < 2; T++)
#pragma unroll
    for (int h = 0; h < 2; h++) {
        int bb = cc[T][h];
        float m0, s0, w0, m1, s1, w1;
        prep_cd(zm, zlv, bb, l, gc,     m0, s0, w0);
        prep_cd(zm, zlv, bb, l, gc + 4, m1, s1, w1);
        u64 mu = pk(m0, m1);
        sC[CSLOT(0, T, 0, h)][lane] = mu;
        sC[CSLOT(1, T, 0, h)][lane] = pk(s0, s1);
        sC[CSLOT(2, T, 0, h)][lane] = pk(w0, w1);
        xt[T][0][h]  = mu;
        err2[T][0][h] = 0ULL;
        if (gc < 2) {
            prep_cd(zm, zlv, bb, l, 8 + gc, m0, s0, w0);
        } else { m0 = 0.f; s0 = 0.f; w0 = 0.f; }
        mu = pk(m0, 0.f);
        sC[CSLOT(0, T, 1, h)][lane] = mu;
        sC[CSLOT(1, T, 1, h)][lane] = pk(s0, 0.f);
        sC[CSLOT(2, T, 1, h)][lane] = pk(w0, 0.f);
        xt[T][1][h]  = mu;
        err2[T][1][h] = 0ULL;
    }
    __syncwarp();

    const u64 dt2 = pk(DTC, DTC);
    const u64 h05 = pk(0.5f, 0.5f);

    // bias values in S C-layout
    const float bs0 = b2[gc];
    const float bs1 = b2[gc + 4];
    const float bs2 = (gc < 2) ? b2[8 + gc] : 0.f;

    // noise pointers per tile
    const float* nz0 = noise + ((size_t)l * NSTEPS * BATCH + cc[0][0]) * LATENT;
    const float* nz1 = noise + ((size_t)l * NSTEPS * BATCH + cc[1][0]) * LATENT;
    const int nzstep = BATCH * LATENT;

#pragma unroll 1
    for (int s = 0; s < NSTEPS; s++) {
        const float tt = (float)(l + s) * DTC;

        // ---- noise gathers for both tiles (prefetch ahead of MMA work) ----
        u64 nzv[2][2][2];
#pragma unroll
        for (int T = 0; T < 2; T++) {
            const float* nA = (T == 0) ? nz0 : nz1;
            const float* nB = nA + 8 * LATENT;
            nzv[T][0][0] = pk(nA[gc], nA[gc + 4]);
            nzv[T][0][1] = pk(nB[gc], nB[gc + 4]);
            nzv[T][1][0] = (gc < 2) ? pk(nA[8 + gc], 0.f) : 0ULL;
            nzv[T][1][1] = (gc < 2) ? pk(nB[8 + gc], 0.f) : 0ULL;
        }
        nz0 += nzstep;
        nz1 += nzstep;

        // ---- build A fragments for both tiles (raw fp32 bits) ----
        u32 A[2][4], E[2][2];
#pragma unroll
        for (int T = 0; T < 2; T++) {
            float x0, x1, y0, y1;
            upk(xt[T][0][0], x0, x1);
            upk(xt[T][0][1], y0, y1);
            A[T][0] = as_u32(x0);
            A[T][1] = as_u32(y0);
            A[T][2] = as_u32(x1);
            A[T][3] = as_u32(y1);

            float xA8, xB8, dmy;
            upk(xt[T][1][0], xA8, dmy);
            upk(xt[T][1][1], xB8, dmy);
            float sA0 = __shfl_sync(0xffffffffu, xA8, lane & ~3);
            float sA1 = __shfl_sync(0xffffffffu, xA8, (lane & ~3) | 1);
            float sB0 = __shfl_sync(0xffffffffu, xB8, lane & ~3);
            float sB1 = __shfl_sync(0xffffffffu, xB8, (lane & ~3) | 1);
            float f0 = (gc == 0) ? sA0 : (gc == 1) ? sA1 : (gc == 2) ? tt : 1.0f;
            float f1 = (gc == 0) ? sB0 : (gc == 1) ? sB1 : (gc == 2) ? tt : 1.0f;
            E[T][0] = as_u32(f0);
            E[T][1] = as_u32(f1);
        }

        // ---- layer-2 accumulators: 8 chains (tile x nt x jt-parity) ----
        float S[2][2][2][4];
#pragma unroll
        for (int T = 0; T < 2; T++) {
            S[T][0][0][0] = bs0; S[T][0][0][1] = bs1; S[T][0][0][2] = bs0; S[T][0][0][3] = bs1;
            S[T][1][0][0] = bs2; S[T][1][0][1] = 0.f; S[T][1][0][2] = bs2; S[T][1][0][3] = 0.f;
#pragma unroll
            for (int q = 0; q < 4; q++) { S[T][0][1][q] = 0.f; S[T][1][1][q] = 0.f; }
        }

#pragma unroll
        for (int jt = 0; jt < 8; jt++) {
            const int par = jt & 1;
            // layer-1 for both tiles (independent chains)
            float C0[4] = {0.f, 0.f, 0.f, 0.f};
            float C1[4] = {0.f, 0.f, 0.f, 0.f};
            mma8(C0, A[0][0], A[0][1], A[0][2], A[0][3], B1h0[jt][0], B1h0[jt][1]);
            mma8(C1, A[1][0], A[1][1], A[1][2], A[1][3], B1h0[jt][0], B1h0[jt][1]);
            mma8(C0, E[0][0], E[0][1], 0u, 0u, B1h1[jt], 0u);
            mma8(C1, E[1][0], E[1][1], 0u, 0u, B1h1[jt], 0u);

            // relu + C->A fragment permute (c0,c2,c1,c3), raw bits
            u32 H0[4], H1[4];
            H0[0] = as_u32(fmaxf(C0[0], 0.f));
            H0[1] = as_u32(fmaxf(C0[2], 0.f));
            H0[2] = as_u32(fmaxf(C0[1], 0.f));
            H0[3] = as_u32(fmaxf(C0[3], 0.f));
            H1[0] = as_u32(fmaxf(C1[0], 0.f));
            H1[1] = as_u32(fmaxf(C1[2], 0.f));
            H1[2] = as_u32(fmaxf(C1[1], 0.f));
            H1[3] = as_u32(fmaxf(C1[3], 0.f));

            mma8(S[0][0][par], H0[0], H0[1], H0[2], H0[3], B2h[jt][0][0], B2h[jt][0][1]);
            mma8(S[1][0][par], H1[0], H1[1], H1[2], H1[3], B2h[jt][0][0], B2h[jt][0][1]);
            mma8(S[0][1][par], H0[0], H0[1], H0[2], H0[3], B2h[jt][1][0], B2h[jt][1][1]);
            mma8(S[1][1][par], H1[0], H1[1], H1[2], H1[3], B2h[jt][1][0], B2h[jt][1][1]);
        }

        // ---- SDE update + score error, both tiles ----
#pragma unroll
        for (int T = 0; T < 2; T++)
#pragma unroll
        for (int nt = 0; nt < 2; nt++) {
            u64 sc0 = pk(S[T][nt][0][0] + S[T][nt][1][0],
                         S[T][nt][0][1] + S[T][nt][1][1]);
            u64 sc1 = pk(S[T][nt][0][2] + S[T][nt][1][2],
                         S[T][nt][0][3] + S[T][nt][1][3]);
            u64 scp[2] = {sc0, sc1};
#pragma unroll
            for (int h = 0; h < 2; h++) {
                u64 mu   = sC[CSLOT(0, T, nt, h)][lane];
                u64 sinv = sC[CSLOT(1, T, nt, h)][lane];
                u64 ssd  = sC[CSLOT(2, T, nt, h)][lane];
                u64 logdx = mul2_(sub2_(mu, xt[T][nt][h]), sinv);
                u64 diff  = sub2_(logdx, scp[h]);
                err2[T][nt][h] = fma2_(diff, diff, err2[T][nt][h]);
                u64 x  = fma2_(mu, dt2, xt[T][nt][h]);
                u64 t1 = mul2_(scp[h], ssd);
                u64 t2 = mul2_(t1, ssd);
                x = fma2_(t2, h05, x);                       // + 0.5*var*score*dt
                xt[T][nt][h] = fma2_(nzv[T][nt][h], ssd, x);
            }
        }
    }

    // ---- outputs (scatter from fragment layout) ----
    const float inv_n = 1.0f / (float)NSTEPS;
#pragma unroll
    for (int T = 0; T < 2; T++)
#pragma unroll
    for (int h = 0; h < 2; h++) {
        int bb = cc[T][h];
        float* oS = out + ((size_t)bb * MAXLEN + l) * LATENT;
        float* oE = oS + (size_t)BATCH * MAXLEN * LATENT;
        float x0, x1, e0, e1;
        upk(xt[T][0][h], x0, x1);
        upk(err2[T][0][h], e0, e1);
        oS[gc]     = x0;
        oS[gc + 4] = x1;
        oE[gc]     = e0 * inv_n;
        oE[gc + 4] = e1 * inv_n;
        if (gc < 2) {
            upk(xt[T][1][h], x0, x1);
            upk(err2[T][1][h], e0, e1);
            oS[8 + gc] = x0;
            oE[8 + gc] = e0 * inv_n;
        }
    }
}

extern "C" void kernel_launch(void* const* d_in, const int* in_sizes, int n_in,
                              void* d_out, int out_size)
{
    const float* zm    = (const float*)d_in[0];  // [512,80,10]
    const float* zlv   = (const float*)d_in[1];  // [512,80,10]
    const float* W1    = (const float*)d_in[2];  // [11,64]
    const float* b1    = (const float*)d_in[3];  // [64]
    const float* W2    = (const float*)d_in[4];  // [64,10]
    const float* b2    = (const float*)d_in[5];  // [10]
    const float* noise = (const float*)d_in[6];  // [80,100,512,10]
    float* out = (float*)d_out;                  // [2,512,80,10]

    const int nblocks = BATCH * MAXLEN / 32;     // 1280 warps, 32 chains each
    vae_mma6_kernel<<<nblocks, 32>>>(zm, zlv, W1, b1, W2, b2, noise, out);
}

// round 13
// speedup vs baseline: 2.1379x; 1.4267x over previous
#include <cuda_runtime.h>

#define LATENT  10
#define MAXLEN  80
#define BATCH   512
#define NSTEPS  100
#define HID     64
#define DTC     0.01f

typedef unsigned long long u64;
typedef unsigned int u32;

// ---------------- packed f32x2 helpers (sm_100+) ----------------
__device__ __forceinline__ u64 pk(float x, float y) {
    u64 r; asm("mov.b64 %0, {%1, %2};" : "=l"(r) : "f"(x), "f"(y)); return r;
}
__device__ __forceinline__ void upk(u64 a, float& x, float& y) {
    asm("mov.b64 {%0, %1}, %2;" : "=f"(x), "=f"(y) : "l"(a));
}
__device__ __forceinline__ u64 fma2_(u64 a, u64 b, u64 c) {
    u64 d; asm("fma.rn.f32x2 %0, %1, %2, %3;" : "=l"(d) : "l"(a), "l"(b), "l"(c)); return d;
}
__device__ __forceinline__ u64 add2_(u64 a, u64 b) {
    u64 d; asm("add.rn.f32x2 %0, %1, %2;" : "=l"(d) : "l"(a), "l"(b)); return d;
}
__device__ __forceinline__ u64 sub2_(u64 a, u64 b) {
    u64 d; asm("sub.rn.f32x2 %0, %1, %2;" : "=l"(d) : "l"(a), "l"(b)); return d;
}

// ---------------- tf32 helpers ----------------
__device__ __forceinline__ u32 cvt_tf32(float x) {           // setup only
    u32 r; asm("cvt.rna.tf32.f32 %0, %1;" : "=r"(r) : "f"(x)); return r;
}
__device__ __forceinline__ u32 as_u32(float x) { return __float_as_uint(x); }

__device__ __forceinline__ void mma8(float* c, u32 a0, u32 a1, u32 a2, u32 a3,
                                     u32 b0, u32 b1) {
    asm("mma.sync.aligned.m16n8k8.row.col.f32.tf32.tf32.f32 "
        "{%0,%1,%2,%3}, {%4,%5,%6,%7}, {%8,%9}, {%0,%1,%2,%3};"
        : "+f"(c[0]), "+f"(c[1]), "+f"(c[2]), "+f"(c[3])
        : "r"(a0), "r"(a1), "r"(a2), "r"(a3), "r"(b0), "r"(b1));
}

// per-(chain, d) SDE raw constants
__device__ __forceinline__ void prep_cd(const float* __restrict__ zm,
                                        const float* __restrict__ zlv,
                                        int bb, int l, int d,
                                        float& mu, float& sinv, float& ssd) {
    const float* zmr = zm  + ((size_t)bb * MAXLEN + l) * LATENT;
    const float* zvr = zlv + ((size_t)bb * MAXLEN + l) * LATENT;
    float zmc = zmr[d];
    float zmp = (l > 0) ? zmr[d - LATENT] : 0.f;
    mu = zmc - zmp;
    float av = (l > 0) ? zvr[d - LATENT] : 0.f;
    float bv = zvr[d];
    float mx = fmaxf(av, bv);
    float sg = mx + log1pf(expf(-fabsf(av - bv)));   // logaddexp
    float sstd = expf(0.5f * sg);
    sinv = 1.f / sg;
    ssd  = sstd * 0.1f;                              // sigma_std * sqrt(dt)
}

// SMEM folded-constant slots: c in {0:nsinv, 1:musinv, 2:mudt, 3:hv, 4:ssd}
#define KSLOT(c, nt, h) (((c) * 2 + (nt)) * 2 + (h))
#define ESLOT(nt, h)    ((nt) * 2 + (h))

// One warp = 16 chains (same l). Single M-tile m16n8k8 tf32 MMA, weights in
// register B-fragments, raw fp32 bits as MMA inputs. SDE constants folded
// into SMEM (frees regs -> 16 CTAs/SM residency at grid 2560). err in SMEM.
// Shuffle-free d8/d9: every lane carries (xt8,xt9); nt1 B-fragment maps even
// n-cols to d8 and odd to d9 so the MMA broadcasts both scores to all lanes.
__global__ void __launch_bounds__(32, 16)
vae_mma7_kernel(const float* __restrict__ zm,
                const float* __restrict__ zlv,
                const float* __restrict__ W1,
                const float* __restrict__ b1,
                const float* __restrict__ W2,
                const float* __restrict__ b2,
                const float* __restrict__ noise,
                float* __restrict__ out)
{
    __shared__ __align__(16) u64 sK[20][32];     // folded SDE constants
    __shared__ __align__(16) u64 sE[4][32];      // err accumulators

    const int lane = threadIdx.x;
    const int r  = lane >> 2;
    const int gc = lane & 3;
    const int base = blockIdx.x * 16;
    const int l   = base >> 9;          // uniform per warp (16 | 512)
    const int bb0 = base & 511;
    const int cA  = bb0 + r;
    const int cB  = bb0 + r + 8;

    // hidden-unit permutation: B-col n (=r) -> j_local
    const int jl = (r & 1) ? (r >> 1) + 4 : (r >> 1);
    const int d8r = 8 + (r & 1);        // nt1 col n=r -> latent d8 (even) / d9 (odd)

    // ---- static weight fragments (single tf32) ----
    u32 B1h0[8][2];                   // layer1 kt0 (features 0-7)
    u32 B1h1[8];                      // layer1 kt1 reg0 (features 8-11)
    u32 B2h[8][2][2];                 // layer2 [jt][nt][reg]

#pragma unroll
    for (int jt = 0; jt < 8; jt++) {
        int j = 8 * jt + jl;
        B1h0[jt][0] = cvt_tf32(W1[gc * HID + j]);
        B1h0[jt][1] = cvt_tf32(W1[(gc + 4) * HID + j]);
        float wt = (gc == 3) ? b1[j] : W1[(8 + gc) * HID + j];
        B1h1[jt] = cvt_tf32(wt);
        B2h[jt][0][0] = cvt_tf32(W2[(8 * jt + gc) * LATENT + jl]);
        B2h[jt][0][1] = cvt_tf32(W2[(8 * jt + gc + 4) * LATENT + jl]);
        B2h[jt][1][0] = cvt_tf32(W2[(8 * jt + gc) * LATENT + d8r]);
        B2h[jt][1][1] = cvt_tf32(W2[(8 * jt + gc + 4) * LATENT + d8r]);
    }

    // ---- SDE state: xt in regs; folded constants + err in SMEM ----
    u64 xt[2][2];
#pragma unroll
    for (int h = 0; h < 2; h++) {
        int bb = (h == 0) ? cA : cB;
        // nt0: d = (gc, gc+4)
        {
            float m0, s0, w0, m1, s1, w1;
            prep_cd(zm, zlv, bb, l, gc,     m0, s0, w0);
            prep_cd(zm, zlv, bb, l, gc + 4, m1, s1, w1);
            sK[KSLOT(0, 0, h)][lane] = pk(-s0, -s1);
            sK[KSLOT(1, 0, h)][lane] = pk(m0 * s0, m1 * s1);
            sK[KSLOT(2, 0, h)][lane] = pk(m0 * DTC, m1 * DTC);
            sK[KSLOT(3, 0, h)][lane] = pk(0.5f * w0 * w0, 0.5f * w1 * w1);
            sK[KSLOT(4, 0, h)][lane] = pk(w0, w1);
            xt[0][h] = pk(m0, m1);
        }
        // nt1: d = (8, 9), redundant on ALL lanes
        {
            float m0, s0, w0, m1, s1, w1;
            prep_cd(zm, zlv, bb, l, 8, m0, s0, w0);
            prep_cd(zm, zlv, bb, l, 9, m1, s1, w1);
            sK[KSLOT(0, 1, h)][lane] = pk(-s0, -s1);
            sK[KSLOT(1, 1, h)][lane] = pk(m0 * s0, m1 * s1);
            sK[KSLOT(2, 1, h)][lane] = pk(m0 * DTC, m1 * DTC);
            sK[KSLOT(3, 1, h)][lane] = pk(0.5f * w0 * w0, 0.5f * w1 * w1);
            sK[KSLOT(4, 1, h)][lane] = pk(w0, w1);
            xt[1][h] = pk(m0, m1);
        }
        sE[ESLOT(0, h)][lane] = 0ULL;
        sE[ESLOT(1, h)][lane] = 0ULL;
    }
    __syncwarp();

    // bias values in S C-layout
    const float bs0 = b2[gc];
    const float bs1 = b2[gc + 4];
    const float b28 = b2[8];
    const float b29 = b2[9];

    const float* nzp = noise + ((size_t)l * NSTEPS * BATCH + cA) * LATENT;
    const int nzstep = BATCH * LATENT;

#pragma unroll 1
    for (int s = 0; s < NSTEPS; s++) {
        const float tt = (float)(l + s) * DTC;

        // ---- noise gathers ----
        const float* nA = nzp;
        const float* nB = nzp + 8 * LATENT;
        u64 nzv[2][2];
        nzv[0][0] = pk(nA[gc], nA[gc + 4]);
        nzv[0][1] = pk(nB[gc], nB[gc + 4]);
        nzv[1][0] = *(const u64*)(nA + 8);    // (d8,d9), 8B-aligned
        nzv[1][1] = *(const u64*)(nB + 8);
        nzp += nzstep;

        // ---- A fragments (raw fp32 bits) ----
        float x0, x1, y0, y1;
        upk(xt[0][0], x0, x1);
        upk(xt[0][1], y0, y1);
        u32 A0 = as_u32(x0);
        u32 A1 = as_u32(y0);
        u32 A2 = as_u32(x1);
        u32 A3 = as_u32(y1);

        float fA8, fA9, fB8, fB9;
        upk(xt[1][0], fA8, fA9);
        upk(xt[1][1], fB8, fB9);
        float f0 = (gc == 0) ? fA8 : (gc == 1) ? fA9 : (gc == 2) ? tt : 1.0f;
        float f1 = (gc == 0) ? fB8 : (gc == 1) ? fB9 : (gc == 2) ? tt : 1.0f;
        u32 E0 = as_u32(f0);
        u32 E1 = as_u32(f1);

        // ---- layer-2 accumulators: 4 chains (nt x jt-parity) ----
        float S[2][2][4];
        S[0][0][0] = bs0; S[0][0][1] = bs1; S[0][0][2] = bs0; S[0][0][3] = bs1;
        S[1][0][0] = b28; S[1][0][1] = b29; S[1][0][2] = b28; S[1][0][3] = b29;
#pragma unroll
        for (int q = 0; q < 4; q++) { S[0][1][q] = 0.f; S[1][1][q] = 0.f; }

#pragma unroll
        for (int jt = 0; jt < 8; jt++) {
            const int par = jt & 1;
            float C[4] = {0.f, 0.f, 0.f, 0.f};
            mma8(C, A0, A1, A2, A3, B1h0[jt][0], B1h0[jt][1]);
            mma8(C, E0, E1, 0u, 0u, B1h1[jt], 0u);

            // relu + C->A fragment permute (c0,c2,c1,c3), raw bits
            u32 H0 = as_u32(fmaxf(C[0], 0.f));
            u32 H1 = as_u32(fmaxf(C[2], 0.f));
            u32 H2 = as_u32(fmaxf(C[1], 0.f));
            u32 H3 = as_u32(fmaxf(C[3], 0.f));

            mma8(S[0][par], H0, H1, H2, H3, B2h[jt][0][0], B2h[jt][0][1]);
            mma8(S[1][par], H0, H1, H2, H3, B2h[jt][1][0], B2h[jt][1][1]);
        }

        // ---- SDE update + score error ----
#pragma unroll
        for (int nt = 0; nt < 2; nt++) {
            u64 scp[2];
            scp[0] = pk(S[nt][0][0] + S[nt][1][0], S[nt][0][1] + S[nt][1][1]);
            scp[1] = pk(S[nt][0][2] + S[nt][1][2], S[nt][0][3] + S[nt][1][3]);
#pragma unroll
            for (int h = 0; h < 2; h++) {
                u64 nsinv  = sK[KSLOT(0, nt, h)][lane];
                u64 musinv = sK[KSLOT(1, nt, h)][lane];
                u64 mudt   = sK[KSLOT(2, nt, h)][lane];
                u64 hv     = sK[KSLOT(3, nt, h)][lane];
                u64 ssd    = sK[KSLOT(4, nt, h)][lane];
                u64 logdx = fma2_(xt[nt][h], nsinv, musinv);   // (mu-xt)*sinv
                u64 diff  = sub2_(logdx, scp[h]);
                u64 e     = sE[ESLOT(nt, h)][lane];
                sE[ESLOT(nt, h)][lane] = fma2_(diff, diff, e);
                u64 x = add2_(xt[nt][h], mudt);                // + mu*dt
                x = fma2_(scp[h], hv, x);                      // + 0.5*var*dt*score
                xt[nt][h] = fma2_(nzv[nt][h], ssd, x);         // + ssd*dW
            }
        }
    }

    // ---- outputs (scatter from fragment layout) ----
    const float inv_n = 1.0f / (float)NSTEPS;
#pragma unroll
    for (int h = 0; h < 2; h++) {
        int bb = (h == 0) ? cA : cB;
        float* oS = out + ((size_t)bb * MAXLEN + l) * LATENT;
        float* oE = oS + (size_t)BATCH * MAXLEN * LATENT;
        float a, b;
        upk(xt[0][h], a, b);
        oS[gc]     = a;
        oS[gc + 4] = b;
        upk(sE[ESLOT(0, h)][lane], a, b);
        oE[gc]     = a * inv_n;
        oE[gc + 4] = b * inv_n;
        if (gc == 0) {
            upk(xt[1][h], a, b);
            *(float2*)(oS + 8) = make_float2(a, b);
            upk(sE[ESLOT(1, h)][lane], a, b);
            *(float2*)(oE + 8) = make_float2(a * inv_n, b * inv_n);
        }
    }
}

extern "C" void kernel_launch(void* const* d_in, const int* in_sizes, int n_in,
                              void* d_out, int out_size)
{
    const float* zm    = (const float*)d_in[0];  // [512,80,10]
    const float* zlv   = (const float*)d_in[1];  // [512,80,10]
    const float* W1    = (const float*)d_in[2];  // [11,64]
    const float* b1    = (const float*)d_in[3];  // [64]
    const float* W2    = (const float*)d_in[4];  // [64,10]
    const float* b2    = (const float*)d_in[5];  // [10]
    const float* noise = (const float*)d_in[6];  // [80,100,512,10]
    float* out = (float*)d_out;                  // [2,512,80,10]

    const int nblocks = BATCH * MAXLEN / 16;     // 2560 warps, 16 chains each
    vae_mma7_kernel<<<nblocks, 32>>>(zm, zlv, W1, b1, W2, b2, noise, out);
}